// round 11
// baseline (speedup 1.0000x reference)
#include <cuda_runtime.h>
#include <cuda_bf16.h>
#include <cstdint>

#define HW 128
#define PER_TENSOR (4 * 64 * HW * HW)
#define NTHP 256
#define NTH  256

// A'': per 128-pixel M-tile (512), 36 chunks (18 hi + 18 lo), each = swizzled
//      [128 pix x 64 k] bf16 tile (16KB).  302 MB.  M=64 CTAs use 8KB halves.
__device__ __nv_bfloat16 Afeat[(size_t)512 * 36 * 8192];
// B'': pass-major, per pass 54 chunks of [Np x 64 k] swizzled bf16. 32.3 MB.
__device__ __nv_bfloat16 Bpack[(size_t)(3 * 192 + 16 * 256) * 3456];

__device__ __forceinline__ uint32_t swz(uint32_t x) { return x ^ ((x >> 3) & 0x70); }
__device__ __forceinline__ int clampi(int v) { return v < 0 ? 0 : (v > 127 ? 127 : v); }
__device__ __forceinline__ uint32_t smem_u32(const void* p) {
    uint32_t a;
    asm("{ .reg .u64 t; cvta.to.shared.u64 t, %1; cvt.u32.u64 %0, t; }" : "=r"(a) : "l"(p));
    return a;
}
__device__ __forceinline__ void ldsm4(uint32_t& r0, uint32_t& r1, uint32_t& r2, uint32_t& r3, uint32_t a) {
    asm volatile("ldmatrix.sync.aligned.m8n8.x4.shared.b16 {%0,%1,%2,%3}, [%4];"
                 : "=r"(r0), "=r"(r1), "=r"(r2), "=r"(r3) : "r"(a));
}
__device__ __forceinline__ void ldsm2(uint32_t& r0, uint32_t& r1, uint32_t a) {
    asm volatile("ldmatrix.sync.aligned.m8n8.x2.shared.b16 {%0,%1}, [%2];"
                 : "=r"(r0), "=r"(r1) : "r"(a));
}
__device__ __forceinline__ void mma16816(float* d, const uint32_t* a, uint32_t b0, uint32_t b1) {
    asm volatile("mma.sync.aligned.m16n8k16.row.col.f32.bf16.bf16.f32 "
                 "{%0,%1,%2,%3}, {%4,%5,%6,%7}, {%8,%9}, {%0,%1,%2,%3};"
                 : "+f"(d[0]), "+f"(d[1]), "+f"(d[2]), "+f"(d[3])
                 : "r"(a[0]), "r"(a[1]), "r"(a[2]), "r"(a[3]), "r"(b0), "r"(b1));
}
__device__ __forceinline__ void cpa16(uint32_t dst, const void* src) {
    asm volatile("cp.async.cg.shared.global [%0], [%1], 16;" :: "r"(dst), "l"(src) : "memory");
}
#define CP_COMMIT() asm volatile("cp.async.commit_group;" ::: "memory")
#define CP_WAIT0()  asm volatile("cp.async.wait_group 0;" ::: "memory")

// ---------------- prep: feat -> bf16 hi/lo swizzled A tiles ----------------
__global__ void prep_feat(const float* __restrict__ x, const float* __restrict__ m) {
    __shared__ __align__(16) __nv_bfloat16 hi_s[128 * 72];
    __shared__ __align__(16) __nv_bfloat16 lo_s[128 * 72];
    const int fc = blockIdx.x % 18;
    const int mt = blockIdx.x / 18;
    const int b = mt >> 7, hrow = mt & 127;
    const int tid = threadIdx.x;
    for (int idx = tid; idx < 64 * 128; idx += NTHP) {
        int pix = idx & 127, fl = idx >> 7;
        int f = fc * 64 + fl;
        const float* src = x; int fr = f;
        if (f >= 576) { src = m; fr = f - 576; }
        int c = fr / 9, tap = fr - c * 9;
        int kh = tap / 3, kw = tap - kh * 3;
        int hh = clampi(hrow + kh - 1), ww = clampi(pix + kw - 1);
        float v = src[(((size_t)b * 64 + c) * 128 + hh) * 128 + ww];
        __nv_bfloat16 h16 = __float2bfloat16(v);
        hi_s[pix * 72 + fl] = h16;
        lo_s[pix * 72 + fl] = __float2bfloat16(v - __bfloat162float(h16));
    }
    __syncthreads();
    uint4* outh = (uint4*)(Afeat + ((size_t)mt * 36 + fc) * 8192);
    uint4* outl = (uint4*)(Afeat + ((size_t)mt * 36 + fc + 18) * 8192);
    for (int e = tid; e < 1024; e += NTHP) {
        uint32_t u = swz((uint32_t)e * 16);
        int pix = u >> 7, k0 = (u & 127) >> 1;
        outh[e] = *(const uint4*)&hi_s[pix * 72 + k0];
        outl[e] = *(const uint4*)&lo_s[pix * 72 + k0];
    }
}

// ---------------- prep: W1/W2 -> B'' (hi,hi,lo) swizzled, permuted ----------
__global__ void prep_B(const float* __restrict__ W1, const float* __restrict__ W2) {
    __shared__ __align__(16) __nv_bfloat16 hi_s[64 * 72];
    __shared__ __align__(16) __nv_bfloat16 lo_s[64 * 72];
    const int fc = blockIdx.x % 18;
    const int gs = blockIdx.x / 18;           // 0..72
    const int tid = threadIdx.x;
    int p, nn0;
    if (gs < 9) { p = gs / 3; nn0 = (gs % 3) * 64; }
    else        { int t = gs - 9; p = 3 + (t >> 2); nn0 = (t & 3) * 64; }
    const int Np = (p < 3) ? 192 : 256;
    for (int idx = tid; idx < 64 * 64; idx += NTHP) {
        int g_l = idx & 63, kk = idx >> 6;
        int f = fc * 64 + kk;
        int nn = nn0 + g_l;
        float v;
        if (p < 3) { int j = p * 192 + nn; v = W1[(size_t)f * 576 + j]; }
        else { int c = nn >> 2, o = (p - 3) * 4 + (nn & 3); v = W2[(size_t)f * 4096 + c * 64 + o]; }
        __nv_bfloat16 h16 = __float2bfloat16(v);
        hi_s[g_l * 72 + kk] = h16;
        lo_s[g_l * 72 + kk] = __float2bfloat16(v - __bfloat162float(h16));
    }
    __syncthreads();
    const size_t pbase = (p < 3) ? (size_t)p * 192 * 3456
                                 : (size_t)3 * 192 * 3456 + (size_t)(p - 3) * 256 * 3456;
    char* bp = (char*)Bpack;
    const size_t cb0 = (pbase + (size_t)(fc     ) * Np * 64) * 2;
    const size_t cb1 = (pbase + (size_t)(fc + 18) * Np * 64) * 2;
    const size_t cb2 = (pbase + (size_t)(fc + 36) * Np * 64) * 2;
    for (int idx = tid; idx < 512; idx += NTHP) {
        int g_l = idx >> 3, kk0 = (idx & 7) * 8;
        uint32_t q = swz((uint32_t)(nn0 + g_l) * 128 + (uint32_t)kk0 * 2);
        uint4 vh = *(const uint4*)&hi_s[g_l * 72 + kk0];
        uint4 vl = *(const uint4*)&lo_s[g_l * 72 + kk0];
        *(uint4*)(bp + cb0 + q) = vh;
        *(uint4*)(bp + cb1 + q) = vh;
        *(uint4*)(bp + cb2 + q) = vl;
    }
}

// ---------------- main kernel: M=64 tiles, 1024 CTAs, 256 threads -----------
#define OFF_A0    0
#define OFF_A1    8192
#define OFF_B0    16384
#define OFF_B1    49152
#define OFF_YR    81920
#define OFF_MR    98560
#define OFF_SR    115200
#define OFF_STAGE 131840
#define SMEM_MAIN 134912

// Single-sync double-buffered pipeline (invariants as before). A chunks are the
// 8KB half-tiles (rows half*64..half*64+63 of the swizzled 128-row tile).
template<int NT8>   // n8 tiles per warp: 3 (Np=192) or 4 (Np=256)
__device__ __forceinline__ void gemm_pass(float (&d)[4][4][4],
    const char* aTh, const char* bP, const char* bNext, int nextNb,
    int tid, uint32_t sb)
{
    const int lane = tid & 31, wn = tid >> 5;      // wn = warp id, 0..7
    #pragma unroll
    for (int mi = 0; mi < 4; mi++)
        #pragma unroll
        for (int ni = 0; ni < NT8; ni++)
            #pragma unroll
            for (int r = 0; r < 4; r++) d[mi][ni][r] = 0.f;

    const uint32_t sA0 = sb + OFF_A0, sA1 = sb + OFF_A1;
    const uint32_t sB0 = sb + OFF_B0, sB1 = sb + OFF_B1;
    const int CB = NT8 * 8192;                     // B chunk bytes

    const uint32_t aRow  = (uint32_t)(((lane & 15)) * 128 + (lane >> 4) * 16);
    const uint32_t bRow  = (uint32_t)((wn * (NT8 * 8) + (lane & 15)) * 128 + (lane >> 4) * 16);
    const uint32_t bRow2 = (uint32_t)((wn * 24 + 16 + (lane & 7)) * 128 + ((lane >> 3) & 1) * 16);

    for (int ck = 0; ck < 54; ck++) {
        const int buf = ck & 1;
        CP_WAIT0();
        __syncthreads();
        const uint32_t dA = buf ? sA0 : sA1;
        const uint32_t dB = buf ? sB0 : sB1;
        if (ck < 53) {
            const int nk = ck + 1, cka = (nk < 36) ? nk : nk - 36;
            const char* aSrc = aTh + (size_t)cka * 16384;
            const char* bSrc = bP + (size_t)nk * CB;
            #pragma unroll
            for (int i = 0; i < 2; i++)       cpa16(dA + (tid + i * NTH) * 16, aSrc + (size_t)(tid + i * NTH) * 16);
            #pragma unroll
            for (int i = 0; i < NT8 * 2; i++) cpa16(dB + (tid + i * NTH) * 16, bSrc + (size_t)(tid + i * NTH) * 16);
            CP_COMMIT();
        } else if (bNext) {
            #pragma unroll
            for (int i = 0; i < 2; i++) cpa16(dA + (tid + i * NTH) * 16, aTh + (size_t)(tid + i * NTH) * 16);
            for (int i = 0; i < nextNb; i++) cpa16(dB + (tid + i * NTH) * 16, bNext + (size_t)(tid + i * NTH) * 16);
            CP_COMMIT();
        }
        const uint32_t aB = buf ? sA1 : sA0;
        const uint32_t bB = buf ? sB1 : sB0;
        #pragma unroll
        for (int kg = 0; kg < 4; kg++) {
            const uint32_t kb = kg * 32;
            uint32_t af[4][4];
            #pragma unroll
            for (int mi = 0; mi < 4; mi++)
                ldsm4(af[mi][0], af[mi][1], af[mi][2], af[mi][3],
                      aB + swz(aRow + mi * 2048 + kb));
            uint32_t b0a[4], b1a[4];
            {
                uint32_t r0, r1, r2, r3;
                ldsm4(r0, r1, r2, r3, bB + swz(bRow + kb));
                b0a[0] = r0; b0a[1] = r1; b1a[0] = r2; b1a[1] = r3;
                if (NT8 == 4) {
                    ldsm4(r0, r1, r2, r3, bB + swz(bRow + 2048 + kb));
                    b0a[2] = r0; b0a[3] = r1; b1a[2] = r2; b1a[3] = r3;
                } else {
                    ldsm2(r0, r1, bB + swz(bRow2 + kb));
                    b0a[2] = r0; b1a[2] = r1;
                }
            }
            #pragma unroll
            for (int mi = 0; mi < 4; mi++)
                #pragma unroll
                for (int ni = 0; ni < NT8; ni++)
                    mma16816(d[mi][ni], af[mi], b0a[ni], b1a[ni]);
        }
    }
}

__device__ __forceinline__ const char* bbase(int p) {
    return (const char*)Bpack + ((p < 3) ? (size_t)p * 192 * 3456
                                         : (size_t)3 * 192 * 3456 + (size_t)(p - 3) * 256 * 3456) * 2;
}

__global__ __launch_bounds__(NTH, 1)
void kpn_main(const float* __restrict__ x, const float* __restrict__ m,
              const float* __restrict__ s, const float* __restrict__ b1,
              const float* __restrict__ b2, float* __restrict__ out)
{
    extern __shared__ __align__(1024) char smc[];
    const uint32_t sb = smem_u32(smc);
    const int tid = threadIdx.x, lane = tid & 31, wn = tid >> 5;
    const int mt = blockIdx.x >> 1, half = blockIdx.x & 1;
    const int b = mt >> 7, hrow = mt & 127;
    const int wbase = half * 64;               // pixel-column base of this CTA

    const char* aTh = (const char*)Afeat + (size_t)mt * 36 * 16384 + (size_t)half * 8192;

    // preload pass 0 chunk 0 into buffer 0
    {
        const char* bSrc = bbase(0);
        #pragma unroll
        for (int i = 0; i < 2; i++) cpa16(sb + OFF_A0 + (tid + i * NTH) * 16, aTh + (size_t)(tid + i * NTH) * 16);
        #pragma unroll
        for (int i = 0; i < 6; i++) cpa16(sb + OFF_B0 + (tid + i * NTH) * 16, bSrc + (size_t)(tid + i * NTH) * 16);
        CP_COMMIT();
    }

    float* yr_s  = (float*)(smc + OFF_YR);
    float* mr_s  = (float*)(smc + OFF_MR);
    float* sr_s  = (float*)(smc + OFF_SR);
    float* stage = (float*)(smc + OFF_STAGE);
    for (int i = tid; i < 64 * 65; i += NTH) { yr_s[i] = 0.f; mr_s[i] = 0.f; sr_s[i] = 0.f; }

    float d[4][4][4];

    for (int p = 0; p < 19; p++) {
        if (p < 3) {
            gemm_pass<3>(d, aTh, bbase(p), bbase(p + 1), (p + 1 < 3) ? 6 : 8, tid, sb);
            // ---- W1 epilogue: build yr/mr/sr ----
            #pragma unroll
            for (int mi = 0; mi < 4; mi++) {
                #pragma unroll
                for (int r = 0; r < 4; r++) {
                    const int pix = mi * 16 + (lane >> 2) + (r >> 1) * 8;
                    #pragma unroll
                    for (int ni = 0; ni < 3; ni++) {
                        const int j = p * 192 + wn * 24 + ni * 8 + (lane & 3) * 2 + (r & 1);
                        const float w1v = d[mi][ni][r] + b1[j];
                        const float aw = fabsf(w1v);
                        const int c = j / 9, tap = j - 9 * c;
                        const int kh = tap / 3, kw = tap - kh * 3;
                        const int hh = clampi(hrow + kh - 1);
                        const int ww = clampi(wbase + pix + kw - 1);
                        const size_t ro = (((size_t)b * 64 + c) * 128 + hh) * 128 + ww;
                        atomicAdd(&yr_s[pix * 65 + c], x[ro] * w1v);
                        atomicAdd(&mr_s[pix * 65 + c], m[ro] * aw);
                        atomicAdd(&sr_s[pix * 65 + c], s[ro] * aw);
                    }
                }
            }
            __syncthreads();
        } else {
            gemm_pass<4>(d, aTh, bbase(p), (p < 18) ? bbase(p + 1) : nullptr, 8, tid, sb);
            // ---- W2 epilogue: outputs o = (p-3)*4 + [0,4) ----
            for (int i = tid; i < 64 * 12; i += NTH) stage[i] = 0.f;
            __syncthreads();
            #pragma unroll
            for (int mi = 0; mi < 4; mi++) {
                #pragma unroll
                for (int r = 0; r < 4; r++) {
                    const int pix = mi * 16 + (lane >> 2) + (r >> 1) * 8;
                    #pragma unroll
                    for (int ni = 0; ni < 4; ni++) {
                        const int nn = wn * 32 + ni * 8 + (lane & 3) * 2 + (r & 1);
                        const int c = nn >> 2, oo = nn & 3;
                        const float v = d[mi][ni][r] + b2[c * 64 + (p - 3) * 4 + oo];
                        const float av = fabsf(v);
                        atomicAdd(&stage[pix * 12 + oo],      yr_s[pix * 65 + c] * v);
                        atomicAdd(&stage[pix * 12 + 4 + oo],  mr_s[pix * 65 + c] * av);
                        atomicAdd(&stage[pix * 12 + 8 + oo],  sr_s[pix * 65 + c] * av);
                    }
                }
            }
            __syncthreads();
            {
                const int px = tid & 63, oo = tid >> 6;
                const int o = (p - 3) * 4 + oo;
                const float y  = stage[px * 12 + oo];
                const float mm = stage[px * 12 + 4 + oo] / stage[px * 12 + 8 + oo];
                const size_t gi = (((size_t)b * 64 + o) * 128 + hrow) * 128 + wbase + px;
                out[gi] = y;
                out[gi + PER_TENSOR] = mm;
                out[gi + 2 * PER_TENSOR] = 1.0f;
            }
            __syncthreads();
        }
    }
}

extern "C" void kernel_launch(void* const* d_in, const int* in_sizes, int n_in,
                              void* d_out, int out_size)
{
    const float* x  = (const float*)d_in[0];
    const float* m  = (const float*)d_in[1];
    const float* s  = (const float*)d_in[2];
    const float* W1 = (const float*)d_in[3];
    const float* b1 = (const float*)d_in[4];
    const float* W2 = (const float*)d_in[5];
    const float* b2 = (const float*)d_in[6];
    float* out = (float*)d_out;

    cudaFuncSetAttribute(kpn_main, cudaFuncAttributeMaxDynamicSharedMemorySize, SMEM_MAIN);

    prep_feat<<<512 * 18, NTHP>>>(x, m);
    prep_B<<<73 * 18, NTHP>>>(W1, W2);
    kpn_main<<<1024, NTH, SMEM_MAIN>>>(x, m, s, b1, b2, out);
}

// round 12
// speedup vs baseline: 1.0020x; 1.0020x over previous
#include <cuda_runtime.h>
#include <cuda_bf16.h>
#include <cstdint>

#define HW 128
#define PER_TENSOR (4 * 64 * HW * HW)
#define NTHP 256
#define NTH  256

// A'': per 128-pixel M-tile (512), 36 chunks (18 hi + 18 lo), each = swizzled
//      [128 pix x 64 k] bf16 tile (16KB).  302 MB.  M=64 CTAs use 8KB halves.
__device__ __nv_bfloat16 Afeat[(size_t)512 * 36 * 8192];
// B'': pass-major, per pass 54 chunks of [Np x 64 k] swizzled bf16. 32.3 MB.
__device__ __nv_bfloat16 Bpack[(size_t)(3 * 192 + 16 * 256) * 3456];

__device__ __forceinline__ uint32_t swz(uint32_t x) { return x ^ ((x >> 3) & 0x70); }
__device__ __forceinline__ int clampi(int v) { return v < 0 ? 0 : (v > 127 ? 127 : v); }
__device__ __forceinline__ uint32_t smem_u32(const void* p) {
    uint32_t a;
    asm("{ .reg .u64 t; cvta.to.shared.u64 t, %1; cvt.u32.u64 %0, t; }" : "=r"(a) : "l"(p));
    return a;
}
__device__ __forceinline__ void ldsm4(uint32_t& r0, uint32_t& r1, uint32_t& r2, uint32_t& r3, uint32_t a) {
    asm volatile("ldmatrix.sync.aligned.m8n8.x4.shared.b16 {%0,%1,%2,%3}, [%4];"
                 : "=r"(r0), "=r"(r1), "=r"(r2), "=r"(r3) : "r"(a));
}
__device__ __forceinline__ void ldsm2(uint32_t& r0, uint32_t& r1, uint32_t a) {
    asm volatile("ldmatrix.sync.aligned.m8n8.x2.shared.b16 {%0,%1}, [%2];"
                 : "=r"(r0), "=r"(r1) : "r"(a));
}
__device__ __forceinline__ void mma16816(float* d, const uint32_t* a, uint32_t b0, uint32_t b1) {
    asm volatile("mma.sync.aligned.m16n8k16.row.col.f32.bf16.bf16.f32 "
                 "{%0,%1,%2,%3}, {%4,%5,%6,%7}, {%8,%9}, {%0,%1,%2,%3};"
                 : "+f"(d[0]), "+f"(d[1]), "+f"(d[2]), "+f"(d[3])
                 : "r"(a[0]), "r"(a[1]), "r"(a[2]), "r"(a[3]), "r"(b0), "r"(b1));
}
__device__ __forceinline__ void cpa16(uint32_t dst, const void* src) {
    asm volatile("cp.async.cg.shared.global [%0], [%1], 16;" :: "r"(dst), "l"(src) : "memory");
}
#define CP_COMMIT() asm volatile("cp.async.commit_group;" ::: "memory")
#define CP_WAIT0()  asm volatile("cp.async.wait_group 0;" ::: "memory")

// ---------------- prep: feat -> bf16 hi/lo swizzled A tiles ----------------
__global__ void prep_feat(const float* __restrict__ x, const float* __restrict__ m) {
    __shared__ __align__(16) __nv_bfloat16 hi_s[128 * 72];
    __shared__ __align__(16) __nv_bfloat16 lo_s[128 * 72];
    const int fc = blockIdx.x % 18;
    const int mt = blockIdx.x / 18;
    const int b = mt >> 7, hrow = mt & 127;
    const int tid = threadIdx.x;
    for (int idx = tid; idx < 64 * 128; idx += NTHP) {
        int pix = idx & 127, fl = idx >> 7;
        int f = fc * 64 + fl;
        const float* src = x; int fr = f;
        if (f >= 576) { src = m; fr = f - 576; }
        int c = fr / 9, tap = fr - c * 9;
        int kh = tap / 3, kw = tap - kh * 3;
        int hh = clampi(hrow + kh - 1), ww = clampi(pix + kw - 1);
        float v = src[(((size_t)b * 64 + c) * 128 + hh) * 128 + ww];
        __nv_bfloat16 h16 = __float2bfloat16(v);
        hi_s[pix * 72 + fl] = h16;
        lo_s[pix * 72 + fl] = __float2bfloat16(v - __bfloat162float(h16));
    }
    __syncthreads();
    uint4* outh = (uint4*)(Afeat + ((size_t)mt * 36 + fc) * 8192);
    uint4* outl = (uint4*)(Afeat + ((size_t)mt * 36 + fc + 18) * 8192);
    for (int e = tid; e < 1024; e += NTHP) {
        uint32_t u = swz((uint32_t)e * 16);
        int pix = u >> 7, k0 = (u & 127) >> 1;
        outh[e] = *(const uint4*)&hi_s[pix * 72 + k0];
        outl[e] = *(const uint4*)&lo_s[pix * 72 + k0];
    }
}

// ---------------- prep: W1/W2 -> B'' (hi,hi,lo) swizzled, permuted ----------
__global__ void prep_B(const float* __restrict__ W1, const float* __restrict__ W2) {
    __shared__ __align__(16) __nv_bfloat16 hi_s[64 * 72];
    __shared__ __align__(16) __nv_bfloat16 lo_s[64 * 72];
    const int fc = blockIdx.x % 18;
    const int gs = blockIdx.x / 18;           // 0..72
    const int tid = threadIdx.x;
    int p, nn0;
    if (gs < 9) { p = gs / 3; nn0 = (gs % 3) * 64; }
    else        { int t = gs - 9; p = 3 + (t >> 2); nn0 = (t & 3) * 64; }
    const int Np = (p < 3) ? 192 : 256;
    for (int idx = tid; idx < 64 * 64; idx += NTHP) {
        int g_l = idx & 63, kk = idx >> 6;
        int f = fc * 64 + kk;
        int nn = nn0 + g_l;
        float v;
        if (p < 3) { int j = p * 192 + nn; v = W1[(size_t)f * 576 + j]; }
        else { int c = nn >> 2, o = (p - 3) * 4 + (nn & 3); v = W2[(size_t)f * 4096 + c * 64 + o]; }
        __nv_bfloat16 h16 = __float2bfloat16(v);
        hi_s[g_l * 72 + kk] = h16;
        lo_s[g_l * 72 + kk] = __float2bfloat16(v - __bfloat162float(h16));
    }
    __syncthreads();
    const size_t pbase = (p < 3) ? (size_t)p * 192 * 3456
                                 : (size_t)3 * 192 * 3456 + (size_t)(p - 3) * 256 * 3456;
    char* bp = (char*)Bpack;
    const size_t cb0 = (pbase + (size_t)(fc     ) * Np * 64) * 2;
    const size_t cb1 = (pbase + (size_t)(fc + 18) * Np * 64) * 2;
    const size_t cb2 = (pbase + (size_t)(fc + 36) * Np * 64) * 2;
    for (int idx = tid; idx < 512; idx += NTHP) {
        int g_l = idx >> 3, kk0 = (idx & 7) * 8;
        uint32_t q = swz((uint32_t)(nn0 + g_l) * 128 + (uint32_t)kk0 * 2);
        uint4 vh = *(const uint4*)&hi_s[g_l * 72 + kk0];
        uint4 vl = *(const uint4*)&lo_s[g_l * 72 + kk0];
        *(uint4*)(bp + cb0 + q) = vh;
        *(uint4*)(bp + cb1 + q) = vh;
        *(uint4*)(bp + cb2 + q) = vl;
    }
}

// ---------------- main kernel: M=64 tiles, 1024 CTAs, 256 threads -----------
#define OFF_A0    0
#define OFF_A1    8192
#define OFF_B0    16384
#define OFF_B1    49152
#define OFF_YR    81920
#define OFF_MR    98560
#define OFF_SR    115200
#define OFF_STAGE 131840
#define SMEM_MAIN 134912

// Single-sync double-buffered pipeline (invariants as before). A chunks are the
// 8KB half-tiles (rows half*64..half*64+63 of the swizzled 128-row tile).
template<int NT8>   // n8 tiles per warp: 3 (Np=192) or 4 (Np=256)
__device__ __forceinline__ void gemm_pass(float (&d)[4][4][4],
    const char* aTh, const char* bP, const char* bNext, int nextNb,
    int tid, uint32_t sb)
{
    const int lane = tid & 31, wn = tid >> 5;      // wn = warp id, 0..7
    #pragma unroll
    for (int mi = 0; mi < 4; mi++)
        #pragma unroll
        for (int ni = 0; ni < NT8; ni++)
            #pragma unroll
            for (int r = 0; r < 4; r++) d[mi][ni][r] = 0.f;

    const uint32_t sA0 = sb + OFF_A0, sA1 = sb + OFF_A1;
    const uint32_t sB0 = sb + OFF_B0, sB1 = sb + OFF_B1;
    const int CB = NT8 * 8192;                     // B chunk bytes

    const uint32_t aRow  = (uint32_t)(((lane & 15)) * 128 + (lane >> 4) * 16);
    const uint32_t bRow  = (uint32_t)((wn * (NT8 * 8) + (lane & 15)) * 128 + (lane >> 4) * 16);
    const uint32_t bRow2 = (uint32_t)((wn * 24 + 16 + (lane & 7)) * 128 + ((lane >> 3) & 1) * 16);

    for (int ck = 0; ck < 54; ck++) {
        const int buf = ck & 1;
        CP_WAIT0();
        __syncthreads();
        const uint32_t dA = buf ? sA0 : sA1;
        const uint32_t dB = buf ? sB0 : sB1;
        if (ck < 53) {
            const int nk = ck + 1, cka = (nk < 36) ? nk : nk - 36;
            const char* aSrc = aTh + (size_t)cka * 16384;
            const char* bSrc = bP + (size_t)nk * CB;
            #pragma unroll
            for (int i = 0; i < 2; i++)       cpa16(dA + (tid + i * NTH) * 16, aSrc + (size_t)(tid + i * NTH) * 16);
            #pragma unroll
            for (int i = 0; i < NT8 * 2; i++) cpa16(dB + (tid + i * NTH) * 16, bSrc + (size_t)(tid + i * NTH) * 16);
            CP_COMMIT();
        } else if (bNext) {
            #pragma unroll
            for (int i = 0; i < 2; i++) cpa16(dA + (tid + i * NTH) * 16, aTh + (size_t)(tid + i * NTH) * 16);
            for (int i = 0; i < nextNb; i++) cpa16(dB + (tid + i * NTH) * 16, bNext + (size_t)(tid + i * NTH) * 16);
            CP_COMMIT();
        }
        const uint32_t aB = buf ? sA1 : sA0;
        const uint32_t bB = buf ? sB1 : sB0;
        #pragma unroll
        for (int kg = 0; kg < 4; kg++) {
            const uint32_t kb = kg * 32;
            uint32_t af[4][4];
            #pragma unroll
            for (int mi = 0; mi < 4; mi++)
                ldsm4(af[mi][0], af[mi][1], af[mi][2], af[mi][3],
                      aB + swz(aRow + mi * 2048 + kb));
            uint32_t b0a[4], b1a[4];
            {
                uint32_t r0, r1, r2, r3;
                ldsm4(r0, r1, r2, r3, bB + swz(bRow + kb));
                b0a[0] = r0; b0a[1] = r1; b1a[0] = r2; b1a[1] = r3;
                if (NT8 == 4) {
                    ldsm4(r0, r1, r2, r3, bB + swz(bRow + 2048 + kb));
                    b0a[2] = r0; b0a[3] = r1; b1a[2] = r2; b1a[3] = r3;
                } else {
                    ldsm2(r0, r1, bB + swz(bRow2 + kb));
                    b0a[2] = r0; b1a[2] = r1;
                }
            }
            #pragma unroll
            for (int mi = 0; mi < 4; mi++)
                #pragma unroll
                for (int ni = 0; ni < NT8; ni++)
                    mma16816(d[mi][ni], af[mi], b0a[ni], b1a[ni]);
        }
    }
}

__device__ __forceinline__ const char* bbase(int p) {
    return (const char*)Bpack + ((p < 3) ? (size_t)p * 192 * 3456
                                         : (size_t)3 * 192 * 3456 + (size_t)(p - 3) * 256 * 3456) * 2;
}

__global__ __launch_bounds__(NTH, 1)
void kpn_main(const float* __restrict__ x, const float* __restrict__ m,
              const float* __restrict__ s, const float* __restrict__ b1,
              const float* __restrict__ b2, float* __restrict__ out)
{
    extern __shared__ __align__(1024) char smc[];
    const uint32_t sb = smem_u32(smc);
    const int tid = threadIdx.x, lane = tid & 31, wn = tid >> 5;
    const int mt = blockIdx.x >> 1, half = blockIdx.x & 1;
    const int b = mt >> 7, hrow = mt & 127;
    const int wbase = half * 64;               // pixel-column base of this CTA

    const char* aTh = (const char*)Afeat + (size_t)mt * 36 * 16384 + (size_t)half * 8192;

    // preload pass 0 chunk 0 into buffer 0
    {
        const char* bSrc = bbase(0);
        #pragma unroll
        for (int i = 0; i < 2; i++) cpa16(sb + OFF_A0 + (tid + i * NTH) * 16, aTh + (size_t)(tid + i * NTH) * 16);
        #pragma unroll
        for (int i = 0; i < 6; i++) cpa16(sb + OFF_B0 + (tid + i * NTH) * 16, bSrc + (size_t)(tid + i * NTH) * 16);
        CP_COMMIT();
    }

    float* yr_s  = (float*)(smc + OFF_YR);
    float* mr_s  = (float*)(smc + OFF_MR);
    float* sr_s  = (float*)(smc + OFF_SR);
    float* stage = (float*)(smc + OFF_STAGE);
    for (int i = tid; i < 64 * 65; i += NTH) { yr_s[i] = 0.f; mr_s[i] = 0.f; sr_s[i] = 0.f; }

    float d[4][4][4];

    for (int p = 0; p < 19; p++) {
        if (p < 3) {
            gemm_pass<3>(d, aTh, bbase(p), bbase(p + 1), (p + 1 < 3) ? 6 : 8, tid, sb);
            // ---- W1 epilogue: build yr/mr/sr ----
            #pragma unroll
            for (int mi = 0; mi < 4; mi++) {
                #pragma unroll
                for (int r = 0; r < 4; r++) {
                    const int pix = mi * 16 + (lane >> 2) + (r >> 1) * 8;
                    #pragma unroll
                    for (int ni = 0; ni < 3; ni++) {
                        const int j = p * 192 + wn * 24 + ni * 8 + (lane & 3) * 2 + (r & 1);
                        const float w1v = d[mi][ni][r] + b1[j];
                        const float aw = fabsf(w1v);
                        const int c = j / 9, tap = j - 9 * c;
                        const int kh = tap / 3, kw = tap - kh * 3;
                        const int hh = clampi(hrow + kh - 1);
                        const int ww = clampi(wbase + pix + kw - 1);
                        const size_t ro = (((size_t)b * 64 + c) * 128 + hh) * 128 + ww;
                        atomicAdd(&yr_s[pix * 65 + c], x[ro] * w1v);
                        atomicAdd(&mr_s[pix * 65 + c], m[ro] * aw);
                        atomicAdd(&sr_s[pix * 65 + c], s[ro] * aw);
                    }
                }
            }
            __syncthreads();
        } else {
            gemm_pass<4>(d, aTh, bbase(p), (p < 18) ? bbase(p + 1) : nullptr, 8, tid, sb);
            // ---- W2 epilogue: outputs o = (p-3)*4 + [0,4) ----
            for (int i = tid; i < 64 * 12; i += NTH) stage[i] = 0.f;
            __syncthreads();
            #pragma unroll
            for (int mi = 0; mi < 4; mi++) {
                #pragma unroll
                for (int r = 0; r < 4; r++) {
                    const int pix = mi * 16 + (lane >> 2) + (r >> 1) * 8;
                    #pragma unroll
                    for (int ni = 0; ni < 4; ni++) {
                        const int nn = wn * 32 + ni * 8 + (lane & 3) * 2 + (r & 1);
                        const int c = nn >> 2, oo = nn & 3;
                        const float v = d[mi][ni][r] + b2[c * 64 + (p - 3) * 4 + oo];
                        const float av = fabsf(v);
                        atomicAdd(&stage[pix * 12 + oo],      yr_s[pix * 65 + c] * v);
                        atomicAdd(&stage[pix * 12 + 4 + oo],  mr_s[pix * 65 + c] * av);
                        atomicAdd(&stage[pix * 12 + 8 + oo],  sr_s[pix * 65 + c] * av);
                    }
                }
            }
            __syncthreads();
            {
                const int px = tid & 63, oo = tid >> 6;
                const int o = (p - 3) * 4 + oo;
                const float y  = stage[px * 12 + oo];
                const float mm = stage[px * 12 + 4 + oo] / stage[px * 12 + 8 + oo];
                const size_t gi = (((size_t)b * 64 + o) * 128 + hrow) * 128 + wbase + px;
                out[gi] = y;
                out[gi + PER_TENSOR] = mm;
                out[gi + 2 * PER_TENSOR] = 1.0f;
            }
            __syncthreads();
        }
    }
}

extern "C" void kernel_launch(void* const* d_in, const int* in_sizes, int n_in,
                              void* d_out, int out_size)
{
    const float* x  = (const float*)d_in[0];
    const float* m  = (const float*)d_in[1];
    const float* s  = (const float*)d_in[2];
    const float* W1 = (const float*)d_in[3];
    const float* b1 = (const float*)d_in[4];
    const float* W2 = (const float*)d_in[5];
    const float* b2 = (const float*)d_in[6];
    float* out = (float*)d_out;

    cudaFuncSetAttribute(kpn_main, cudaFuncAttributeMaxDynamicSharedMemorySize, SMEM_MAIN);

    prep_feat<<<512 * 18, NTHP>>>(x, m);
    prep_B<<<73 * 18, NTHP>>>(W1, W2);
    kpn_main<<<1024, NTH, SMEM_MAIN>>>(x, m, s, b1, b2, out);
}

// round 13
// speedup vs baseline: 1.0022x; 1.0002x over previous
#include <cuda_runtime.h>
#include <cuda_bf16.h>
#include <cstdint>

#define HW 128
#define PER_TENSOR (4 * 64 * HW * HW)
#define NTHP 256
#define NTH  256

// A'': per 128-pixel M-tile (512), 36 chunks (18 hi + 18 lo), each = swizzled
//      [128 pix x 64 k] bf16 tile (16KB).  302 MB.  M=64 CTAs use 8KB halves.
__device__ __nv_bfloat16 Afeat[(size_t)512 * 36 * 8192];
// B'': pass-major, per pass 54 chunks of [Np x 64 k] swizzled bf16. 32.3 MB.
__device__ __nv_bfloat16 Bpack[(size_t)(3 * 192 + 16 * 256) * 3456];

__device__ __forceinline__ uint32_t swz(uint32_t x) { return x ^ ((x >> 3) & 0x70); }
__device__ __forceinline__ int clampi(int v) { return v < 0 ? 0 : (v > 127 ? 127 : v); }
__device__ __forceinline__ uint32_t smem_u32(const void* p) {
    uint32_t a;
    asm("{ .reg .u64 t; cvta.to.shared.u64 t, %1; cvt.u32.u64 %0, t; }" : "=r"(a) : "l"(p));
    return a;
}
__device__ __forceinline__ void ldsm4(uint32_t& r0, uint32_t& r1, uint32_t& r2, uint32_t& r3, uint32_t a) {
    asm volatile("ldmatrix.sync.aligned.m8n8.x4.shared.b16 {%0,%1,%2,%3}, [%4];"
                 : "=r"(r0), "=r"(r1), "=r"(r2), "=r"(r3) : "r"(a));
}
__device__ __forceinline__ void ldsm2(uint32_t& r0, uint32_t& r1, uint32_t a) {
    asm volatile("ldmatrix.sync.aligned.m8n8.x2.shared.b16 {%0,%1}, [%2];"
                 : "=r"(r0), "=r"(r1) : "r"(a));
}
__device__ __forceinline__ void mma16816(float* d, const uint32_t* a, uint32_t b0, uint32_t b1) {
    asm volatile("mma.sync.aligned.m16n8k16.row.col.f32.bf16.bf16.f32 "
                 "{%0,%1,%2,%3}, {%4,%5,%6,%7}, {%8,%9}, {%0,%1,%2,%3};"
                 : "+f"(d[0]), "+f"(d[1]), "+f"(d[2]), "+f"(d[3])
                 : "r"(a[0]), "r"(a[1]), "r"(a[2]), "r"(a[3]), "r"(b0), "r"(b1));
}
__device__ __forceinline__ void cpa16(uint32_t dst, const void* src) {
    asm volatile("cp.async.cg.shared.global [%0], [%1], 16;" :: "r"(dst), "l"(src) : "memory");
}
#define CP_COMMIT() asm volatile("cp.async.commit_group;" ::: "memory")
#define CP_WAIT0()  asm volatile("cp.async.wait_group 0;" ::: "memory")

// ---------------- prep: feat -> bf16 hi/lo swizzled A tiles ----------------
__global__ void prep_feat(const float* __restrict__ x, const float* __restrict__ m) {
    __shared__ __align__(16) __nv_bfloat16 hi_s[128 * 72];
    __shared__ __align__(16) __nv_bfloat16 lo_s[128 * 72];
    const int fc = blockIdx.x % 18;
    const int mt = blockIdx.x / 18;
    const int b = mt >> 7, hrow = mt & 127;
    const int tid = threadIdx.x;
    for (int idx = tid; idx < 64 * 128; idx += NTHP) {
        int pix = idx & 127, fl = idx >> 7;
        int f = fc * 64 + fl;
        const float* src = x; int fr = f;
        if (f >= 576) { src = m; fr = f - 576; }
        int c = fr / 9, tap = fr - c * 9;
        int kh = tap / 3, kw = tap - kh * 3;
        int hh = clampi(hrow + kh - 1), ww = clampi(pix + kw - 1);
        float v = src[(((size_t)b * 64 + c) * 128 + hh) * 128 + ww];
        __nv_bfloat16 h16 = __float2bfloat16(v);
        hi_s[pix * 72 + fl] = h16;
        lo_s[pix * 72 + fl] = __float2bfloat16(v - __bfloat162float(h16));
    }
    __syncthreads();
    uint4* outh = (uint4*)(Afeat + ((size_t)mt * 36 + fc) * 8192);
    uint4* outl = (uint4*)(Afeat + ((size_t)mt * 36 + fc + 18) * 8192);
    for (int e = tid; e < 1024; e += NTHP) {
        uint32_t u = swz((uint32_t)e * 16);
        int pix = u >> 7, k0 = (u & 127) >> 1;
        outh[e] = *(const uint4*)&hi_s[pix * 72 + k0];
        outl[e] = *(const uint4*)&lo_s[pix * 72 + k0];
    }
}

// ---------------- prep: W1/W2 -> B'' (hi,hi,lo) swizzled, permuted ----------
__global__ void prep_B(const float* __restrict__ W1, const float* __restrict__ W2) {
    __shared__ __align__(16) __nv_bfloat16 hi_s[64 * 72];
    __shared__ __align__(16) __nv_bfloat16 lo_s[64 * 72];
    const int fc = blockIdx.x % 18;
    const int gs = blockIdx.x / 18;           // 0..72
    const int tid = threadIdx.x;
    int p, nn0;
    if (gs < 9) { p = gs / 3; nn0 = (gs % 3) * 64; }
    else        { int t = gs - 9; p = 3 + (t >> 2); nn0 = (t & 3) * 64; }
    const int Np = (p < 3) ? 192 : 256;
    for (int idx = tid; idx < 64 * 64; idx += NTHP) {
        int g_l = idx & 63, kk = idx >> 6;
        int f = fc * 64 + kk;
        int nn = nn0 + g_l;
        float v;
        if (p < 3) { int j = p * 192 + nn; v = W1[(size_t)f * 576 + j]; }
        else { int c = nn >> 2, o = (p - 3) * 4 + (nn & 3); v = W2[(size_t)f * 4096 + c * 64 + o]; }
        __nv_bfloat16 h16 = __float2bfloat16(v);
        hi_s[g_l * 72 + kk] = h16;
        lo_s[g_l * 72 + kk] = __float2bfloat16(v - __bfloat162float(h16));
    }
    __syncthreads();
    const size_t pbase = (p < 3) ? (size_t)p * 192 * 3456
                                 : (size_t)3 * 192 * 3456 + (size_t)(p - 3) * 256 * 3456;
    char* bp = (char*)Bpack;
    const size_t cb0 = (pbase + (size_t)(fc     ) * Np * 64) * 2;
    const size_t cb1 = (pbase + (size_t)(fc + 18) * Np * 64) * 2;
    const size_t cb2 = (pbase + (size_t)(fc + 36) * Np * 64) * 2;
    for (int idx = tid; idx < 512; idx += NTHP) {
        int g_l = idx >> 3, kk0 = (idx & 7) * 8;
        uint32_t q = swz((uint32_t)(nn0 + g_l) * 128 + (uint32_t)kk0 * 2);
        uint4 vh = *(const uint4*)&hi_s[g_l * 72 + kk0];
        uint4 vl = *(const uint4*)&lo_s[g_l * 72 + kk0];
        *(uint4*)(bp + cb0 + q) = vh;
        *(uint4*)(bp + cb1 + q) = vh;
        *(uint4*)(bp + cb2 + q) = vl;
    }
}

// ---------------- main kernel: M=64 tiles, 1024 CTAs, 256 threads -----------
#define OFF_A0    0
#define OFF_A1    8192
#define OFF_B0    16384
#define OFF_B1    49152
#define OFF_YR    81920
#define OFF_MR    98560
#define OFF_SR    115200
#define OFF_STAGE 131840
#define SMEM_MAIN 134912

// Single-sync double-buffered pipeline (invariants as before). A chunks are the
// 8KB half-tiles (rows half*64..half*64+63 of the swizzled 128-row tile).
template<int NT8>   // n8 tiles per warp: 3 (Np=192) or 4 (Np=256)
__device__ __forceinline__ void gemm_pass(float (&d)[4][4][4],
    const char* aTh, const char* bP, const char* bNext, int nextNb,
    int tid, uint32_t sb)
{
    const int lane = tid & 31, wn = tid >> 5;      // wn = warp id, 0..7
    #pragma unroll
    for (int mi = 0; mi < 4; mi++)
        #pragma unroll
        for (int ni = 0; ni < NT8; ni++)
            #pragma unroll
            for (int r = 0; r < 4; r++) d[mi][ni][r] = 0.f;

    const uint32_t sA0 = sb + OFF_A0, sA1 = sb + OFF_A1;
    const uint32_t sB0 = sb + OFF_B0, sB1 = sb + OFF_B1;
    const int CB = NT8 * 8192;                     // B chunk bytes

    const uint32_t aRow  = (uint32_t)(((lane & 15)) * 128 + (lane >> 4) * 16);
    const uint32_t bRow  = (uint32_t)((wn * (NT8 * 8) + (lane & 15)) * 128 + (lane >> 4) * 16);
    const uint32_t bRow2 = (uint32_t)((wn * 24 + 16 + (lane & 7)) * 128 + ((lane >> 3) & 1) * 16);

    for (int ck = 0; ck < 54; ck++) {
        const int buf = ck & 1;
        CP_WAIT0();
        __syncthreads();
        const uint32_t dA = buf ? sA0 : sA1;
        const uint32_t dB = buf ? sB0 : sB1;
        if (ck < 53) {
            const int nk = ck + 1, cka = (nk < 36) ? nk : nk - 36;
            const char* aSrc = aTh + (size_t)cka * 16384;
            const char* bSrc = bP + (size_t)nk * CB;
            #pragma unroll
            for (int i = 0; i < 2; i++)       cpa16(dA + (tid + i * NTH) * 16, aSrc + (size_t)(tid + i * NTH) * 16);
            #pragma unroll
            for (int i = 0; i < NT8 * 2; i++) cpa16(dB + (tid + i * NTH) * 16, bSrc + (size_t)(tid + i * NTH) * 16);
            CP_COMMIT();
        } else if (bNext) {
            #pragma unroll
            for (int i = 0; i < 2; i++) cpa16(dA + (tid + i * NTH) * 16, aTh + (size_t)(tid + i * NTH) * 16);
            for (int i = 0; i < nextNb; i++) cpa16(dB + (tid + i * NTH) * 16, bNext + (size_t)(tid + i * NTH) * 16);
            CP_COMMIT();
        }
        const uint32_t aB = buf ? sA1 : sA0;
        const uint32_t bB = buf ? sB1 : sB0;
        #pragma unroll
        for (int kg = 0; kg < 4; kg++) {
            const uint32_t kb = kg * 32;
            uint32_t af[4][4];
            #pragma unroll
            for (int mi = 0; mi < 4; mi++)
                ldsm4(af[mi][0], af[mi][1], af[mi][2], af[mi][3],
                      aB + swz(aRow + mi * 2048 + kb));
            uint32_t b0a[4], b1a[4];
            {
                uint32_t r0, r1, r2, r3;
                ldsm4(r0, r1, r2, r3, bB + swz(bRow + kb));
                b0a[0] = r0; b0a[1] = r1; b1a[0] = r2; b1a[1] = r3;
                if (NT8 == 4) {
                    ldsm4(r0, r1, r2, r3, bB + swz(bRow + 2048 + kb));
                    b0a[2] = r0; b0a[3] = r1; b1a[2] = r2; b1a[3] = r3;
                } else {
                    ldsm2(r0, r1, bB + swz(bRow2 + kb));
                    b0a[2] = r0; b1a[2] = r1;
                }
            }
            #pragma unroll
            for (int mi = 0; mi < 4; mi++)
                #pragma unroll
                for (int ni = 0; ni < NT8; ni++)
                    mma16816(d[mi][ni], af[mi], b0a[ni], b1a[ni]);
        }
    }
}

__device__ __forceinline__ const char* bbase(int p) {
    return (const char*)Bpack + ((p < 3) ? (size_t)p * 192 * 3456
                                         : (size_t)3 * 192 * 3456 + (size_t)(p - 3) * 256 * 3456) * 2;
}

__global__ __launch_bounds__(NTH, 1)
void kpn_main(const float* __restrict__ x, const float* __restrict__ m,
              const float* __restrict__ s, const float* __restrict__ b1,
              const float* __restrict__ b2, float* __restrict__ out)
{
    extern __shared__ __align__(1024) char smc[];
    const uint32_t sb = smem_u32(smc);
    const int tid = threadIdx.x, lane = tid & 31, wn = tid >> 5;
    const int mt = blockIdx.x >> 1, half = blockIdx.x & 1;
    const int b = mt >> 7, hrow = mt & 127;
    const int wbase = half * 64;               // pixel-column base of this CTA

    const char* aTh = (const char*)Afeat + (size_t)mt * 36 * 16384 + (size_t)half * 8192;

    // preload pass 0 chunk 0 into buffer 0
    {
        const char* bSrc = bbase(0);
        #pragma unroll
        for (int i = 0; i < 2; i++) cpa16(sb + OFF_A0 + (tid + i * NTH) * 16, aTh + (size_t)(tid + i * NTH) * 16);
        #pragma unroll
        for (int i = 0; i < 6; i++) cpa16(sb + OFF_B0 + (tid + i * NTH) * 16, bSrc + (size_t)(tid + i * NTH) * 16);
        CP_COMMIT();
    }

    float* yr_s  = (float*)(smc + OFF_YR);
    float* mr_s  = (float*)(smc + OFF_MR);
    float* sr_s  = (float*)(smc + OFF_SR);
    float* stage = (float*)(smc + OFF_STAGE);
    for (int i = tid; i < 64 * 65; i += NTH) { yr_s[i] = 0.f; mr_s[i] = 0.f; sr_s[i] = 0.f; }

    float d[4][4][4];

    for (int p = 0; p < 19; p++) {
        if (p < 3) {
            gemm_pass<3>(d, aTh, bbase(p), bbase(p + 1), (p + 1 < 3) ? 6 : 8, tid, sb);
            // ---- W1 epilogue: build yr/mr/sr ----
            #pragma unroll
            for (int mi = 0; mi < 4; mi++) {
                #pragma unroll
                for (int r = 0; r < 4; r++) {
                    const int pix = mi * 16 + (lane >> 2) + (r >> 1) * 8;
                    #pragma unroll
                    for (int ni = 0; ni < 3; ni++) {
                        const int j = p * 192 + wn * 24 + ni * 8 + (lane & 3) * 2 + (r & 1);
                        const float w1v = d[mi][ni][r] + b1[j];
                        const float aw = fabsf(w1v);
                        const int c = j / 9, tap = j - 9 * c;
                        const int kh = tap / 3, kw = tap - kh * 3;
                        const int hh = clampi(hrow + kh - 1);
                        const int ww = clampi(wbase + pix + kw - 1);
                        const size_t ro = (((size_t)b * 64 + c) * 128 + hh) * 128 + ww;
                        atomicAdd(&yr_s[pix * 65 + c], x[ro] * w1v);
                        atomicAdd(&mr_s[pix * 65 + c], m[ro] * aw);
                        atomicAdd(&sr_s[pix * 65 + c], s[ro] * aw);
                    }
                }
            }
            __syncthreads();
        } else {
            gemm_pass<4>(d, aTh, bbase(p), (p < 18) ? bbase(p + 1) : nullptr, 8, tid, sb);
            // ---- W2 epilogue: outputs o = (p-3)*4 + [0,4) ----
            for (int i = tid; i < 64 * 12; i += NTH) stage[i] = 0.f;
            __syncthreads();
            #pragma unroll
            for (int mi = 0; mi < 4; mi++) {
                #pragma unroll
                for (int r = 0; r < 4; r++) {
                    const int pix = mi * 16 + (lane >> 2) + (r >> 1) * 8;
                    #pragma unroll
                    for (int ni = 0; ni < 4; ni++) {
                        const int nn = wn * 32 + ni * 8 + (lane & 3) * 2 + (r & 1);
                        const int c = nn >> 2, oo = nn & 3;
                        const float v = d[mi][ni][r] + b2[c * 64 + (p - 3) * 4 + oo];
                        const float av = fabsf(v);
                        atomicAdd(&stage[pix * 12 + oo],      yr_s[pix * 65 + c] * v);
                        atomicAdd(&stage[pix * 12 + 4 + oo],  mr_s[pix * 65 + c] * av);
                        atomicAdd(&stage[pix * 12 + 8 + oo],  sr_s[pix * 65 + c] * av);
                    }
                }
            }
            __syncthreads();
            {
                const int px = tid & 63, oo = tid >> 6;
                const int o = (p - 3) * 4 + oo;
                const float y  = stage[px * 12 + oo];
                const float mm = stage[px * 12 + 4 + oo] / stage[px * 12 + 8 + oo];
                const size_t gi = (((size_t)b * 64 + o) * 128 + hrow) * 128 + wbase + px;
                out[gi] = y;
                out[gi + PER_TENSOR] = mm;
                out[gi + 2 * PER_TENSOR] = 1.0f;
            }
            __syncthreads();
        }
    }
}

extern "C" void kernel_launch(void* const* d_in, const int* in_sizes, int n_in,
                              void* d_out, int out_size)
{
    const float* x  = (const float*)d_in[0];
    const float* m  = (const float*)d_in[1];
    const float* s  = (const float*)d_in[2];
    const float* W1 = (const float*)d_in[3];
    const float* b1 = (const float*)d_in[4];
    const float* W2 = (const float*)d_in[5];
    const float* b2 = (const float*)d_in[6];
    float* out = (float*)d_out;

    cudaFuncSetAttribute(kpn_main, cudaFuncAttributeMaxDynamicSharedMemorySize, SMEM_MAIN);

    prep_feat<<<512 * 18, NTHP>>>(x, m);
    prep_B<<<73 * 18, NTHP>>>(W1, W2);
    kpn_main<<<1024, NTH, SMEM_MAIN>>>(x, m, s, b1, b2, out);
}

// round 14
// speedup vs baseline: 1.0025x; 1.0003x over previous
#include <cuda_runtime.h>
#include <cuda_bf16.h>
#include <cstdint>

#define HW 128
#define PER_TENSOR (4 * 64 * HW * HW)
#define NTHP 256
#define NTH  256

// A'': per 128-pixel M-tile (512), 36 chunks (18 hi + 18 lo), each = swizzled
//      [128 pix x 64 k] bf16 tile (16KB).  302 MB.  M=64 CTAs use 8KB halves.
__device__ __nv_bfloat16 Afeat[(size_t)512 * 36 * 8192];
// B'': pass-major, per pass 54 chunks of [Np x 64 k] swizzled bf16. 32.3 MB.
__device__ __nv_bfloat16 Bpack[(size_t)(3 * 192 + 16 * 256) * 3456];

__device__ __forceinline__ uint32_t swz(uint32_t x) { return x ^ ((x >> 3) & 0x70); }
__device__ __forceinline__ int clampi(int v) { return v < 0 ? 0 : (v > 127 ? 127 : v); }
__device__ __forceinline__ uint32_t smem_u32(const void* p) {
    uint32_t a;
    asm("{ .reg .u64 t; cvta.to.shared.u64 t, %1; cvt.u32.u64 %0, t; }" : "=r"(a) : "l"(p));
    return a;
}
__device__ __forceinline__ void ldsm4(uint32_t& r0, uint32_t& r1, uint32_t& r2, uint32_t& r3, uint32_t a) {
    asm volatile("ldmatrix.sync.aligned.m8n8.x4.shared.b16 {%0,%1,%2,%3}, [%4];"
                 : "=r"(r0), "=r"(r1), "=r"(r2), "=r"(r3) : "r"(a));
}
__device__ __forceinline__ void ldsm2(uint32_t& r0, uint32_t& r1, uint32_t a) {
    asm volatile("ldmatrix.sync.aligned.m8n8.x2.shared.b16 {%0,%1}, [%2];"
                 : "=r"(r0), "=r"(r1) : "r"(a));
}
__device__ __forceinline__ void mma16816(float* d, const uint32_t* a, uint32_t b0, uint32_t b1) {
    asm volatile("mma.sync.aligned.m16n8k16.row.col.f32.bf16.bf16.f32 "
                 "{%0,%1,%2,%3}, {%4,%5,%6,%7}, {%8,%9}, {%0,%1,%2,%3};"
                 : "+f"(d[0]), "+f"(d[1]), "+f"(d[2]), "+f"(d[3])
                 : "r"(a[0]), "r"(a[1]), "r"(a[2]), "r"(a[3]), "r"(b0), "r"(b1));
}
__device__ __forceinline__ void cpa16(uint32_t dst, const void* src) {
    asm volatile("cp.async.cg.shared.global [%0], [%1], 16;" :: "r"(dst), "l"(src) : "memory");
}
#define CP_COMMIT() asm volatile("cp.async.commit_group;" ::: "memory")
#define CP_WAIT0()  asm volatile("cp.async.wait_group 0;" ::: "memory")

// ---------------- prep: feat -> bf16 hi/lo swizzled A tiles ----------------
__global__ void prep_feat(const float* __restrict__ x, const float* __restrict__ m) {
    __shared__ __align__(16) __nv_bfloat16 hi_s[128 * 72];
    __shared__ __align__(16) __nv_bfloat16 lo_s[128 * 72];
    const int fc = blockIdx.x % 18;
    const int mt = blockIdx.x / 18;
    const int b = mt >> 7, hrow = mt & 127;
    const int tid = threadIdx.x;
    for (int idx = tid; idx < 64 * 128; idx += NTHP) {
        int pix = idx & 127, fl = idx >> 7;
        int f = fc * 64 + fl;
        const float* src = x; int fr = f;
        if (f >= 576) { src = m; fr = f - 576; }
        int c = fr / 9, tap = fr - c * 9;
        int kh = tap / 3, kw = tap - kh * 3;
        int hh = clampi(hrow + kh - 1), ww = clampi(pix + kw - 1);
        float v = src[(((size_t)b * 64 + c) * 128 + hh) * 128 + ww];
        __nv_bfloat16 h16 = __float2bfloat16(v);
        hi_s[pix * 72 + fl] = h16;
        lo_s[pix * 72 + fl] = __float2bfloat16(v - __bfloat162float(h16));
    }
    __syncthreads();
    uint4* outh = (uint4*)(Afeat + ((size_t)mt * 36 + fc) * 8192);
    uint4* outl = (uint4*)(Afeat + ((size_t)mt * 36 + fc + 18) * 8192);
    for (int e = tid; e < 1024; e += NTHP) {
        uint32_t u = swz((uint32_t)e * 16);
        int pix = u >> 7, k0 = (u & 127) >> 1;
        outh[e] = *(const uint4*)&hi_s[pix * 72 + k0];
        outl[e] = *(const uint4*)&lo_s[pix * 72 + k0];
    }
}

// ---------------- prep: W1/W2 -> B'' (hi,hi,lo) swizzled, permuted ----------
__global__ void prep_B(const float* __restrict__ W1, const float* __restrict__ W2) {
    __shared__ __align__(16) __nv_bfloat16 hi_s[64 * 72];
    __shared__ __align__(16) __nv_bfloat16 lo_s[64 * 72];
    const int fc = blockIdx.x % 18;
    const int gs = blockIdx.x / 18;           // 0..72
    const int tid = threadIdx.x;
    int p, nn0;
    if (gs < 9) { p = gs / 3; nn0 = (gs % 3) * 64; }
    else        { int t = gs - 9; p = 3 + (t >> 2); nn0 = (t & 3) * 64; }
    const int Np = (p < 3) ? 192 : 256;
    for (int idx = tid; idx < 64 * 64; idx += NTHP) {
        int g_l = idx & 63, kk = idx >> 6;
        int f = fc * 64 + kk;
        int nn = nn0 + g_l;
        float v;
        if (p < 3) { int j = p * 192 + nn; v = W1[(size_t)f * 576 + j]; }
        else { int c = nn >> 2, o = (p - 3) * 4 + (nn & 3); v = W2[(size_t)f * 4096 + c * 64 + o]; }
        __nv_bfloat16 h16 = __float2bfloat16(v);
        hi_s[g_l * 72 + kk] = h16;
        lo_s[g_l * 72 + kk] = __float2bfloat16(v - __bfloat162float(h16));
    }
    __syncthreads();
    const size_t pbase = (p < 3) ? (size_t)p * 192 * 3456
                                 : (size_t)3 * 192 * 3456 + (size_t)(p - 3) * 256 * 3456;
    char* bp = (char*)Bpack;
    const size_t cb0 = (pbase + (size_t)(fc     ) * Np * 64) * 2;
    const size_t cb1 = (pbase + (size_t)(fc + 18) * Np * 64) * 2;
    const size_t cb2 = (pbase + (size_t)(fc + 36) * Np * 64) * 2;
    for (int idx = tid; idx < 512; idx += NTHP) {
        int g_l = idx >> 3, kk0 = (idx & 7) * 8;
        uint32_t q = swz((uint32_t)(nn0 + g_l) * 128 + (uint32_t)kk0 * 2);
        uint4 vh = *(const uint4*)&hi_s[g_l * 72 + kk0];
        uint4 vl = *(const uint4*)&lo_s[g_l * 72 + kk0];
        *(uint4*)(bp + cb0 + q) = vh;
        *(uint4*)(bp + cb1 + q) = vh;
        *(uint4*)(bp + cb2 + q) = vl;
    }
}

// ---------------- main kernel: M=64 tiles, 1024 CTAs, 256 threads -----------
#define OFF_A0    0
#define OFF_A1    8192
#define OFF_B0    16384
#define OFF_B1    49152
#define OFF_YR    81920
#define OFF_MR    98560
#define OFF_SR    115200
#define OFF_STAGE 131840
#define SMEM_MAIN 134912

// Single-sync double-buffered pipeline (invariants as before). A chunks are the
// 8KB half-tiles (rows half*64..half*64+63 of the swizzled 128-row tile).
template<int NT8>   // n8 tiles per warp: 3 (Np=192) or 4 (Np=256)
__device__ __forceinline__ void gemm_pass(float (&d)[4][4][4],
    const char* aTh, const char* bP, const char* bNext, int nextNb,
    int tid, uint32_t sb)
{
    const int lane = tid & 31, wn = tid >> 5;      // wn = warp id, 0..7
    #pragma unroll
    for (int mi = 0; mi < 4; mi++)
        #pragma unroll
        for (int ni = 0; ni < NT8; ni++)
            #pragma unroll
            for (int r = 0; r < 4; r++) d[mi][ni][r] = 0.f;

    const uint32_t sA0 = sb + OFF_A0, sA1 = sb + OFF_A1;
    const uint32_t sB0 = sb + OFF_B0, sB1 = sb + OFF_B1;
    const int CB = NT8 * 8192;                     // B chunk bytes

    const uint32_t aRow  = (uint32_t)(((lane & 15)) * 128 + (lane >> 4) * 16);
    const uint32_t bRow  = (uint32_t)((wn * (NT8 * 8) + (lane & 15)) * 128 + (lane >> 4) * 16);
    const uint32_t bRow2 = (uint32_t)((wn * 24 + 16 + (lane & 7)) * 128 + ((lane >> 3) & 1) * 16);

    for (int ck = 0; ck < 54; ck++) {
        const int buf = ck & 1;
        CP_WAIT0();
        __syncthreads();
        const uint32_t dA = buf ? sA0 : sA1;
        const uint32_t dB = buf ? sB0 : sB1;
        if (ck < 53) {
            const int nk = ck + 1, cka = (nk < 36) ? nk : nk - 36;
            const char* aSrc = aTh + (size_t)cka * 16384;
            const char* bSrc = bP + (size_t)nk * CB;
            #pragma unroll
            for (int i = 0; i < 2; i++)       cpa16(dA + (tid + i * NTH) * 16, aSrc + (size_t)(tid + i * NTH) * 16);
            #pragma unroll
            for (int i = 0; i < NT8 * 2; i++) cpa16(dB + (tid + i * NTH) * 16, bSrc + (size_t)(tid + i * NTH) * 16);
            CP_COMMIT();
        } else if (bNext) {
            #pragma unroll
            for (int i = 0; i < 2; i++) cpa16(dA + (tid + i * NTH) * 16, aTh + (size_t)(tid + i * NTH) * 16);
            for (int i = 0; i < nextNb; i++) cpa16(dB + (tid + i * NTH) * 16, bNext + (size_t)(tid + i * NTH) * 16);
            CP_COMMIT();
        }
        const uint32_t aB = buf ? sA1 : sA0;
        const uint32_t bB = buf ? sB1 : sB0;
        #pragma unroll
        for (int kg = 0; kg < 4; kg++) {
            const uint32_t kb = kg * 32;
            uint32_t af[4][4];
            #pragma unroll
            for (int mi = 0; mi < 4; mi++)
                ldsm4(af[mi][0], af[mi][1], af[mi][2], af[mi][3],
                      aB + swz(aRow + mi * 2048 + kb));
            uint32_t b0a[4], b1a[4];
            {
                uint32_t r0, r1, r2, r3;
                ldsm4(r0, r1, r2, r3, bB + swz(bRow + kb));
                b0a[0] = r0; b0a[1] = r1; b1a[0] = r2; b1a[1] = r3;
                if (NT8 == 4) {
                    ldsm4(r0, r1, r2, r3, bB + swz(bRow + 2048 + kb));
                    b0a[2] = r0; b0a[3] = r1; b1a[2] = r2; b1a[3] = r3;
                } else {
                    ldsm2(r0, r1, bB + swz(bRow2 + kb));
                    b0a[2] = r0; b1a[2] = r1;
                }
            }
            #pragma unroll
            for (int mi = 0; mi < 4; mi++)
                #pragma unroll
                for (int ni = 0; ni < NT8; ni++)
                    mma16816(d[mi][ni], af[mi], b0a[ni], b1a[ni]);
        }
    }
}

__device__ __forceinline__ const char* bbase(int p) {
    return (const char*)Bpack + ((p < 3) ? (size_t)p * 192 * 3456
                                         : (size_t)3 * 192 * 3456 + (size_t)(p - 3) * 256 * 3456) * 2;
}

__global__ __launch_bounds__(NTH, 1)
void kpn_main(const float* __restrict__ x, const float* __restrict__ m,
              const float* __restrict__ s, const float* __restrict__ b1,
              const float* __restrict__ b2, float* __restrict__ out)
{
    extern __shared__ __align__(1024) char smc[];
    const uint32_t sb = smem_u32(smc);
    const int tid = threadIdx.x, lane = tid & 31, wn = tid >> 5;
    const int mt = blockIdx.x >> 1, half = blockIdx.x & 1;
    const int b = mt >> 7, hrow = mt & 127;
    const int wbase = half * 64;               // pixel-column base of this CTA

    const char* aTh = (const char*)Afeat + (size_t)mt * 36 * 16384 + (size_t)half * 8192;

    // preload pass 0 chunk 0 into buffer 0
    {
        const char* bSrc = bbase(0);
        #pragma unroll
        for (int i = 0; i < 2; i++) cpa16(sb + OFF_A0 + (tid + i * NTH) * 16, aTh + (size_t)(tid + i * NTH) * 16);
        #pragma unroll
        for (int i = 0; i < 6; i++) cpa16(sb + OFF_B0 + (tid + i * NTH) * 16, bSrc + (size_t)(tid + i * NTH) * 16);
        CP_COMMIT();
    }

    float* yr_s  = (float*)(smc + OFF_YR);
    float* mr_s  = (float*)(smc + OFF_MR);
    float* sr_s  = (float*)(smc + OFF_SR);
    float* stage = (float*)(smc + OFF_STAGE);
    for (int i = tid; i < 64 * 65; i += NTH) { yr_s[i] = 0.f; mr_s[i] = 0.f; sr_s[i] = 0.f; }

    float d[4][4][4];

    for (int p = 0; p < 19; p++) {
        if (p < 3) {
            gemm_pass<3>(d, aTh, bbase(p), bbase(p + 1), (p + 1 < 3) ? 6 : 8, tid, sb);
            // ---- W1 epilogue: build yr/mr/sr ----
            #pragma unroll
            for (int mi = 0; mi < 4; mi++) {
                #pragma unroll
                for (int r = 0; r < 4; r++) {
                    const int pix = mi * 16 + (lane >> 2) + (r >> 1) * 8;
                    #pragma unroll
                    for (int ni = 0; ni < 3; ni++) {
                        const int j = p * 192 + wn * 24 + ni * 8 + (lane & 3) * 2 + (r & 1);
                        const float w1v = d[mi][ni][r] + b1[j];
                        const float aw = fabsf(w1v);
                        const int c = j / 9, tap = j - 9 * c;
                        const int kh = tap / 3, kw = tap - kh * 3;
                        const int hh = clampi(hrow + kh - 1);
                        const int ww = clampi(wbase + pix + kw - 1);
                        const size_t ro = (((size_t)b * 64 + c) * 128 + hh) * 128 + ww;
                        atomicAdd(&yr_s[pix * 65 + c], x[ro] * w1v);
                        atomicAdd(&mr_s[pix * 65 + c], m[ro] * aw);
                        atomicAdd(&sr_s[pix * 65 + c], s[ro] * aw);
                    }
                }
            }
            __syncthreads();
        } else {
            gemm_pass<4>(d, aTh, bbase(p), (p < 18) ? bbase(p + 1) : nullptr, 8, tid, sb);
            // ---- W2 epilogue: outputs o = (p-3)*4 + [0,4) ----
            for (int i = tid; i < 64 * 12; i += NTH) stage[i] = 0.f;
            __syncthreads();
            #pragma unroll
            for (int mi = 0; mi < 4; mi++) {
                #pragma unroll
                for (int r = 0; r < 4; r++) {
                    const int pix = mi * 16 + (lane >> 2) + (r >> 1) * 8;
                    #pragma unroll
                    for (int ni = 0; ni < 4; ni++) {
                        const int nn = wn * 32 + ni * 8 + (lane & 3) * 2 + (r & 1);
                        const int c = nn >> 2, oo = nn & 3;
                        const float v = d[mi][ni][r] + b2[c * 64 + (p - 3) * 4 + oo];
                        const float av = fabsf(v);
                        atomicAdd(&stage[pix * 12 + oo],      yr_s[pix * 65 + c] * v);
                        atomicAdd(&stage[pix * 12 + 4 + oo],  mr_s[pix * 65 + c] * av);
                        atomicAdd(&stage[pix * 12 + 8 + oo],  sr_s[pix * 65 + c] * av);
                    }
                }
            }
            __syncthreads();
            {
                const int px = tid & 63, oo = tid >> 6;
                const int o = (p - 3) * 4 + oo;
                const float y  = stage[px * 12 + oo];
                const float mm = stage[px * 12 + 4 + oo] / stage[px * 12 + 8 + oo];
                const size_t gi = (((size_t)b * 64 + o) * 128 + hrow) * 128 + wbase + px;
                out[gi] = y;
                out[gi + PER_TENSOR] = mm;
                out[gi + 2 * PER_TENSOR] = 1.0f;
            }
            __syncthreads();
        }
    }
}

extern "C" void kernel_launch(void* const* d_in, const int* in_sizes, int n_in,
                              void* d_out, int out_size)
{
    const float* x  = (const float*)d_in[0];
    const float* m  = (const float*)d_in[1];
    const float* s  = (const float*)d_in[2];
    const float* W1 = (const float*)d_in[3];
    const float* b1 = (const float*)d_in[4];
    const float* W2 = (const float*)d_in[5];
    const float* b2 = (const float*)d_in[6];
    float* out = (float*)d_out;

    cudaFuncSetAttribute(kpn_main, cudaFuncAttributeMaxDynamicSharedMemorySize, SMEM_MAIN);

    prep_feat<<<512 * 18, NTHP>>>(x, m);
    prep_B<<<73 * 18, NTHP>>>(W1, W2);
    kpn_main<<<1024, NTH, SMEM_MAIN>>>(x, m, s, b1, b2, out);
}